// round 16
// baseline (speedup 1.0000x reference)
#include <cuda_runtime.h>
#include <cstdint>
#include <math.h>

#define N_JOINTS 50
#define ROW 150
#define THREADS 256
#define WARPS_PER_CTA 8
#define TOTAL_ROWS (128 * 1024)
#define ROWGROUPS (TOTAL_ROWS / WARPS_PER_CTA)    // 16384 groups of 8 rows
#define GRID 1480                                  // 148 SMs x 10 CTAs
#define DOT_FLOOR 1e-30f

// Per-block partials, fully overwritten every launch.
__device__ float g_part_abs[GRID];
__device__ float g_part_cos[GRID];
// atomicInc wraps to 0 after GRID increments -> deterministic across replays.
__device__ unsigned int g_count = 0;

// Fused bone: direct global reads of joints a (3*bi) and b (3*nj) in row base.
// Adds joint-a L1 term (each joint is 'a' of exactly one bone).
__device__ __forceinline__ void bone_direct(
    const float* __restrict__ pr, const float* __restrict__ tr,
    int a, int b, float& abs_sum, float& cos_sum)
{
    float pa0 = __ldg(pr + a),     pa1 = __ldg(pr + a + 1), pa2 = __ldg(pr + a + 2);
    float pb0 = __ldg(pr + b),     pb1 = __ldg(pr + b + 1), pb2 = __ldg(pr + b + 2);
    float ta0 = __ldg(tr + a),     ta1 = __ldg(tr + a + 1), ta2 = __ldg(tr + a + 2);
    float tb0 = __ldg(tr + b),     tb1 = __ldg(tr + b + 1), tb2 = __ldg(tr + b + 2);

    abs_sum += fabsf(pa0 - ta0) + fabsf(pa1 - ta1) + fabsf(pa2 - ta2);

    float pd0 = pa0 - pb0, pd1 = pa1 - pb1, pd2 = pa2 - pb2;
    float td0 = ta0 - tb0, td1 = ta1 - tb1, td2 = ta2 - tb2;

    float pdot  = fmaf(pd0, pd0, fmaf(pd1, pd1, pd2 * pd2));
    float tdot  = fmaf(td0, td0, fmaf(td1, td1, td2 * td2));
    float ptdot = fmaf(pd0, td0, fmaf(pd1, td1, pd2 * td2));

    float pinv = rsqrtf(fmaxf(pdot, DOT_FLOOR));
    float tinv = rsqrtf(fmaxf(tdot, DOT_FLOOR));
    cos_sum += (ptdot * pinv) * tinv;
}

__global__ __launch_bounds__(THREADS) void bone_loss_kernel(
    const float* __restrict__ preds,
    const float* __restrict__ targets,
    float* __restrict__ out)
{
    __shared__ float s_abs[WARPS_PER_CTA];
    __shared__ float s_cos[WARPS_PER_CTA];
    __shared__ bool s_last;

    const int tid = threadIdx.x;
    const int wid = tid >> 5;
    const int lid = tid & 31;

    float abs_sum = 0.0f;
    float cos_sum = 0.0f;

    // grid-stride over groups of 8 rows; warp owns one row per group
    for (int g = blockIdx.x; g < ROWGROUPS; g += GRID) {
        const long long row = (long long)g * WARPS_PER_CTA + wid;
        const float* pr = preds   + row * ROW;
        const float* tr = targets + row * ROW;

        // pass 1: bones bi = lid (0..31), b = a+3 (never wraps)
        {
            const int a = 3 * lid;
            bone_direct(pr, tr, a, a + 3, abs_sum, cos_sum);
        }
        // pass 2: bones bi = lid+32 (32..49), lanes 0..17; wrap at bi==49
        if (lid < 18) {
            const int bi = lid + 32;
            const int nj = (bi == N_JOINTS - 1) ? 0 : bi + 1;
            bone_direct(pr, tr, 3 * bi, 3 * nj, abs_sum, cos_sum);
        }
    }

    // ---- warp + block reduction ----
    #pragma unroll
    for (int off = 16; off > 0; off >>= 1) {
        abs_sum += __shfl_down_sync(0xFFFFFFFFu, abs_sum, off);
        cos_sum += __shfl_down_sync(0xFFFFFFFFu, cos_sum, off);
    }
    if (lid == 0) { s_abs[wid] = abs_sum; s_cos[wid] = cos_sum; }
    __syncthreads();

    // ---- publish partial, detect last block ----
    if (tid == 0) {
        float ba = 0.0f, bc = 0.0f;
        #pragma unroll
        for (int w = 0; w < WARPS_PER_CTA; w++) { ba += s_abs[w]; bc += s_cos[w]; }
        g_part_abs[blockIdx.x] = ba;
        g_part_cos[blockIdx.x] = bc;
        __threadfence();
        unsigned int v = atomicInc(&g_count, GRID - 1); // wraps to 0 on last
        s_last = (v == GRID - 1);
    }
    __syncthreads();

    // ---- last block: final reduction over all partials (L2-resident) ----
    if (s_last) {
        double a = 0.0, c = 0.0;
        for (int i = tid; i < GRID; i += THREADS) {
            a += (double)g_part_abs[i];
            c += (double)g_part_cos[i];
        }
        #pragma unroll
        for (int off = 16; off > 0; off >>= 1) {
            a += __shfl_down_sync(0xFFFFFFFFu, a, off);
            c += __shfl_down_sync(0xFFFFFFFFu, c, off);
        }
        __shared__ double sh_a[WARPS_PER_CTA], sh_c[WARPS_PER_CTA];
        if (lid == 0) { sh_a[wid] = a; sh_c[wid] = c; }
        __syncthreads();
        if (tid == 0) {
            double ta = 0.0, tc = 0.0;
            #pragma unroll
            for (int w = 0; w < WARPS_PER_CTA; w++) { ta += sh_a[w]; tc += sh_c[w]; }
            const double NB = (double)TOTAL_ROWS * (double)N_JOINTS; // bones
            const double N  = (double)TOTAL_ROWS * (double)ROW;      // elements
            double sq_total = 2.0 * NB - 2.0 * tc;
            out[0] = (float)((ta / N + 0.1 * (sq_total / N)) * 0.1);
        }
    }
}

extern "C" void kernel_launch(void* const* d_in, const int* in_sizes, int n_in,
                              void* d_out, int out_size) {
    const float* preds   = (const float*)d_in[0];
    const float* targets = (const float*)d_in[1];
    float* out = (float*)d_out;

    bone_loss_kernel<<<GRID, THREADS>>>(preds, targets, out);
}

// round 17
// speedup vs baseline: 1.4370x; 1.4370x over previous
#include <cuda_runtime.h>
#include <cstdint>
#include <math.h>

#define N_JOINTS 50
#define ROW 150
#define THREADS 256
#define WARPS_PER_CTA 8
#define TOTAL_ROWS (128 * 1024)
#define WTILE_ROWS 2
#define WTILE_ELEMS (WTILE_ROWS * ROW)            // 300 floats per tensor
#define WTILE_VECS (WTILE_ELEMS / 4)              // 75 float4
#define N_WTILES (TOTAL_ROWS / WTILE_ROWS)        // 65536
#define GRID 740                                   // 148 SMs x 5 CTAs
#define GWARPS (GRID * WARPS_PER_CTA)             // 5920
#define DOT_FLOOR 1e-30f

// Per-block partials, fully overwritten every launch.
__device__ float g_part_abs[GRID];
__device__ float g_part_cos[GRID];
// atomicInc wraps to 0 after GRID increments -> deterministic across replays.
__device__ unsigned int g_count = 0;

__device__ __forceinline__ void cp_async16(unsigned saddr, const void* gaddr) {
    asm volatile("cp.async.cg.shared.global [%0], [%1], 16;\n"
                 :: "r"(saddr), "l"(gaddr));
}
#define CP_COMMIT() asm volatile("cp.async.commit_group;\n" ::: "memory")
#define CP_WAIT1()  asm volatile("cp.async.wait_group 1;\n" ::: "memory")

// Two consecutive bones sharing middle joint B.
// Joints: A at float offset o (even), B at o+3, C at oc (even).
// Vector loads: A = f2[o] + f[o+2]; B = f[o+3] + f2[o+4]; C = f2[oc] + f[oc+2].
// Folds L1 terms for joints A and B (each joint is 'a' of exactly one bone).
__device__ __forceinline__ void bone_pair(
    const float* __restrict__ cp, const float* __restrict__ ct,
    int o, int oc, float& abs_sum, float& cos_sum)
{
    float2 pA01 = *(const float2*)(cp + o);
    float  pA2  = cp[o + 2];
    float  pB0  = cp[o + 3];
    float2 pB12 = *(const float2*)(cp + o + 4);
    float2 pC01 = *(const float2*)(cp + oc);
    float  pC2  = cp[oc + 2];

    float2 tA01 = *(const float2*)(ct + o);
    float  tA2  = ct[o + 2];
    float  tB0  = ct[o + 3];
    float2 tB12 = *(const float2*)(ct + o + 4);
    float2 tC01 = *(const float2*)(ct + oc);
    float  tC2  = ct[oc + 2];

    abs_sum += fabsf(pA01.x - tA01.x) + fabsf(pA01.y - tA01.y) + fabsf(pA2 - tA2)
             + fabsf(pB0  - tB0)      + fabsf(pB12.x - tB12.x) + fabsf(pB12.y - tB12.y);

    // bone 1: A -> B
    {
        float pd0 = pA01.x - pB0,    pd1 = pA01.y - pB12.x, pd2 = pA2 - pB12.y;
        float td0 = tA01.x - tB0,    td1 = tA01.y - tB12.x, td2 = tA2 - tB12.y;
        float pdot  = fmaf(pd0, pd0, fmaf(pd1, pd1, pd2 * pd2));
        float tdot  = fmaf(td0, td0, fmaf(td1, td1, td2 * td2));
        float ptdot = fmaf(pd0, td0, fmaf(pd1, td1, pd2 * td2));
        float pinv = rsqrtf(fmaxf(pdot, DOT_FLOOR));
        float tinv = rsqrtf(fmaxf(tdot, DOT_FLOOR));
        cos_sum += (ptdot * pinv) * tinv;
    }
    // bone 2: B -> C
    {
        float pd0 = pB0    - pC01.x, pd1 = pB12.x - pC01.y, pd2 = pB12.y - pC2;
        float td0 = tB0    - tC01.x, td1 = tB12.x - tC01.y, td2 = tB12.y - tC2;
        float pdot  = fmaf(pd0, pd0, fmaf(pd1, pd1, pd2 * pd2));
        float tdot  = fmaf(td0, td0, fmaf(td1, td1, td2 * td2));
        float ptdot = fmaf(pd0, td0, fmaf(pd1, td1, pd2 * td2));
        float pinv = rsqrtf(fmaxf(pdot, DOT_FLOOR));
        float tinv = rsqrtf(fmaxf(tdot, DOT_FLOOR));
        cos_sum += (ptdot * pinv) * tinv;
    }
}

__global__ __launch_bounds__(THREADS) void bone_loss_kernel(
    const float* __restrict__ preds,
    const float* __restrict__ targets,
    float* __restrict__ out)
{
    // Warp-private double buffers: no block-level sync in the hot loop.
    __shared__ float sp[WARPS_PER_CTA][2][WTILE_ELEMS];
    __shared__ float st[WARPS_PER_CTA][2][WTILE_ELEMS];
    __shared__ float s_abs[WARPS_PER_CTA];
    __shared__ float s_cos[WARPS_PER_CTA];
    __shared__ bool s_last;

    const int tid = threadIdx.x;
    const int wid = tid >> 5;
    const int lid = tid & 31;

    float abs_sum = 0.0f;
    float cos_sum = 0.0f;

    int wt = blockIdx.x * WARPS_PER_CTA + wid;   // this warp's first tile
    int buf = 0;

    // prologue: stage first warp-tile into buf 0
    {
        const float4* pg = (const float4*)preds   + (long long)wt * WTILE_VECS;
        const float4* tg = (const float4*)targets + (long long)wt * WTILE_VECS;
        unsigned sp_s = (unsigned)__cvta_generic_to_shared(&sp[wid][0][0]);
        unsigned st_s = (unsigned)__cvta_generic_to_shared(&st[wid][0][0]);
        for (int i = lid; i < WTILE_VECS; i += 32) {
            cp_async16(sp_s + i * 16, pg + i);
            cp_async16(st_s + i * 16, tg + i);
        }
        CP_COMMIT();
    }

    for (; wt < N_WTILES; wt += GWARPS) {
        // ---- stage next warp-tile into the other buffer ----
        const int next = wt + GWARPS;
        if (next < N_WTILES) {
            const float4* pg = (const float4*)preds   + (long long)next * WTILE_VECS;
            const float4* tg = (const float4*)targets + (long long)next * WTILE_VECS;
            unsigned sp_s = (unsigned)__cvta_generic_to_shared(&sp[wid][buf ^ 1][0]);
            unsigned st_s = (unsigned)__cvta_generic_to_shared(&st[wid][buf ^ 1][0]);
            for (int i = lid; i < WTILE_VECS; i += 32) {
                cp_async16(sp_s + i * 16, pg + i);
                cp_async16(st_s + i * 16, tg + i);
            }
        }
        CP_COMMIT();           // commit (possibly empty) group every iteration
        CP_WAIT1();            // this warp's current tile is complete
        __syncwarp();

        const float* cp = sp[wid][buf];
        const float* ct = st[wid][buf];

        // ---- pair pass: 2 rows x 25 pairs = 50 pairs = 100 bones ----
        // iteration 1: pair k = lid (0..31); row = k >= 25
        {
            const int k  = lid;
            const int r  = (k >= 25) ? 1 : 0;
            const int kk = k - 25 * r;
            const int roff = r * ROW;
            const int o  = roff + 6 * kk;
            const int oc = (kk == 24) ? roff : o + 6;
            bone_pair(cp, ct, o, oc, abs_sum, cos_sum);
        }
        // iteration 2: pair k = lid + 32 (32..49) -> row 1, kk = lid + 7 (7..24)
        if (lid < 18) {
            const int kk = lid + 7;
            const int o  = ROW + 6 * kk;
            const int oc = (kk == 24) ? ROW : o + 6;
            bone_pair(cp, ct, o, oc, abs_sum, cos_sum);
        }
        __syncwarp();          // all lanes done reading buf before next overwrite
        buf ^= 1;
    }

    // ---- warp + block reduction ----
    #pragma unroll
    for (int off = 16; off > 0; off >>= 1) {
        abs_sum += __shfl_down_sync(0xFFFFFFFFu, abs_sum, off);
        cos_sum += __shfl_down_sync(0xFFFFFFFFu, cos_sum, off);
    }
    if (lid == 0) { s_abs[wid] = abs_sum; s_cos[wid] = cos_sum; }
    __syncthreads();

    // ---- publish partial, detect last block ----
    if (tid == 0) {
        float ba = 0.0f, bc = 0.0f;
        #pragma unroll
        for (int w = 0; w < WARPS_PER_CTA; w++) { ba += s_abs[w]; bc += s_cos[w]; }
        g_part_abs[blockIdx.x] = ba;
        g_part_cos[blockIdx.x] = bc;
        __threadfence();
        unsigned int v = atomicInc(&g_count, GRID - 1); // wraps to 0 on last
        s_last = (v == GRID - 1);
    }
    __syncthreads();

    // ---- last block: final reduction over all partials (L2-resident) ----
    if (s_last) {
        double a = 0.0, c = 0.0;
        for (int i = tid; i < GRID; i += THREADS) {
            a += (double)g_part_abs[i];
            c += (double)g_part_cos[i];
        }
        #pragma unroll
        for (int off = 16; off > 0; off >>= 1) {
            a += __shfl_down_sync(0xFFFFFFFFu, a, off);
            c += __shfl_down_sync(0xFFFFFFFFu, c, off);
        }
        __shared__ double sh_a[WARPS_PER_CTA], sh_c[WARPS_PER_CTA];
        if (lid == 0) { sh_a[wid] = a; sh_c[wid] = c; }
        __syncthreads();
        if (tid == 0) {
            double ta = 0.0, tc = 0.0;
            #pragma unroll
            for (int w = 0; w < WARPS_PER_CTA; w++) { ta += sh_a[w]; tc += sh_c[w]; }
            const double NB = (double)TOTAL_ROWS * (double)N_JOINTS; // bones
            const double N  = (double)TOTAL_ROWS * (double)ROW;      // elements
            double sq_total = 2.0 * NB - 2.0 * tc;
            out[0] = (float)((ta / N + 0.1 * (sq_total / N)) * 0.1);
        }
    }
}

extern "C" void kernel_launch(void* const* d_in, const int* in_sizes, int n_in,
                              void* d_out, int out_size) {
    const float* preds   = (const float*)d_in[0];
    const float* targets = (const float*)d_in[1];
    float* out = (float*)d_out;

    bone_loss_kernel<<<GRID, THREADS>>>(preds, targets, out);
}